// round 1
// baseline (speedup 1.0000x reference)
#include <cuda_runtime.h>
#include <math.h>

// ---------------- problem constants ----------------
constexpr int BB   = 4;
constexpr int CC   = 512;
constexpr int TT   = 16;
constexpr int HWc  = 1024;          // 32*32
constexpr int NN   = BB * HWc;      // 4096 sequences
constexpr int MM   = NN * TT;       // 65536 rows
constexpr int NH   = 8;
constexpr int CH   = 64;            // head dim
constexpr int GRP  = 32;
constexpr int CPG  = CC / GRP;      // 16
constexpr int C3   = 3 * CC;        // 1536
constexpr float EPSF = 1e-6f;

// ---------------- scratch (static device globals; no allocation) ----------------
__device__ float g_mean  [BB * GRP * HWc];
__device__ float g_rstd  [BB * GRP * HWc];
__device__ float g_normed[(size_t)MM * CC];   // [M,512] K-contiguous
__device__ float g_qkv   [(size_t)MM * C3];   // [M,1536]
__device__ float g_att   [(size_t)MM * CC];   // [M,512]
__device__ float g_pout  [(size_t)MM * CC];   // [M,512]

// ---------------- 1) group-norm statistics ----------------
// one block per (b, group); 256 threads, each owns 4 hw lanes (coalesced)
__global__ __launch_bounds__(256) void gn_stats(const float* __restrict__ x) {
    int bg = blockIdx.x;             // 0..127
    int b  = bg >> 5;
    int g  = bg & 31;
    int tid = threadIdx.x;
    float sum[4] = {0.f,0.f,0.f,0.f};
    float sq [4] = {0.f,0.f,0.f,0.f};
    const float* base = x + ((size_t)b * CC + (size_t)g * CPG) * TT * HWc;
    for (int ct = 0; ct < CPG * TT; ct++) {
        const float* p = base + (size_t)ct * HWc;   // ct = c_local*16 + t (contiguous in memory)
        #pragma unroll
        for (int i = 0; i < 4; i++) {
            float v = p[tid + i * 256];
            sum[i] += v;
            sq[i]  += v * v;
        }
    }
    #pragma unroll
    for (int i = 0; i < 4; i++) {
        int hw = tid + i * 256;
        float m   = sum[i] * (1.0f / 256.0f);
        float var = sq[i]  * (1.0f / 256.0f) - m * m;
        g_mean[(size_t)bg * HWc + hw] = m;
        g_rstd[(size_t)bg * HWc + hw] = rsqrtf(var + EPSF);
    }
}

// ---------------- 2) normalize + transpose to [M,512] ----------------
// block handles 32 channels x 32 hw for fixed (b,t). 256 threads.
__global__ __launch_bounds__(256) void norm_tr(const float* __restrict__ x,
                                               const float* __restrict__ gamma,
                                               const float* __restrict__ beta) {
    __shared__ float tile[32][33];
    int bx  = blockIdx.x;
    int hwt = bx & 31;
    int ct  = (bx >> 5) & 15;
    int t   = (bx >> 9) & 15;
    int b   = bx >> 13;
    int tid = threadIdx.x;

    // load: coalesced over hw
    {
        int hw_l = tid & 31;
        int c_l0 = tid >> 5;
        int hw   = hwt * 32 + hw_l;
        #pragma unroll
        for (int p = 0; p < 4; p++) {
            int c_l = c_l0 + p * 8;
            int c   = ct * 32 + c_l;
            int g   = c >> 4;
            float v = x[(((size_t)b * CC + c) * TT + t) * HWc + hw];
            size_t si = ((size_t)(b * GRP + g)) * HWc + hw;
            v = (v - g_mean[si]) * g_rstd[si] * gamma[c] + beta[c];
            tile[c_l][hw_l] = v;
        }
    }
    __syncthreads();
    // store: coalesced over c
    {
        int c_l   = tid & 31;
        int hw_l0 = tid >> 5;
        #pragma unroll
        for (int p = 0; p < 4; p++) {
            int hw_l = hw_l0 + p * 8;
            int hw   = hwt * 32 + hw_l;
            size_t m = ((size_t)(b * HWc + hw)) * TT + t;
            g_normed[m * CC + ct * 32 + c_l] = tile[c_l][hw_l];
        }
    }
}

// ---------------- 3/5) SGEMM: C[M,N] = A[M,512] * W[N,512]^T + bias ----------------
// 128x128 block tile, BK=16, 256 threads, 8x8 per thread.
template <int LDCN>
__device__ __forceinline__ void sgemm_body(const float* __restrict__ A,
                                           const float* __restrict__ Bw,
                                           const float* __restrict__ bias,
                                           float* __restrict__ Cout) {
    constexpr int K = 512;
    __shared__ float As[16][128];
    __shared__ float Bs[16][128];

    int m0 = blockIdx.x * 128;
    int o0 = blockIdx.y * 128;
    int tid = threadIdx.x;
    int tx = tid & 15;
    int ty = tid >> 4;

    int lrow = tid >> 2;          // 0..63
    int lcol = (tid & 3) * 4;     // 0,4,8,12
    const float* Aptr = A  + (size_t)(m0 + lrow) * K + lcol;
    const float* Bptr = Bw + (size_t)(o0 + lrow) * K + lcol;

    float acc[8][8];
    #pragma unroll
    for (int i = 0; i < 8; i++)
        #pragma unroll
        for (int j = 0; j < 8; j++) acc[i][j] = 0.f;

    for (int kt = 0; kt < K; kt += 16) {
        float4 a0 = *(const float4*)(Aptr + kt);
        float4 a1 = *(const float4*)(Aptr + (size_t)64 * K + kt);
        float4 b0 = *(const float4*)(Bptr + kt);
        float4 b1 = *(const float4*)(Bptr + (size_t)64 * K + kt);
        __syncthreads();
        As[lcol + 0][lrow] = a0.x; As[lcol + 1][lrow] = a0.y;
        As[lcol + 2][lrow] = a0.z; As[lcol + 3][lrow] = a0.w;
        As[lcol + 0][lrow + 64] = a1.x; As[lcol + 1][lrow + 64] = a1.y;
        As[lcol + 2][lrow + 64] = a1.z; As[lcol + 3][lrow + 64] = a1.w;
        Bs[lcol + 0][lrow] = b0.x; Bs[lcol + 1][lrow] = b0.y;
        Bs[lcol + 2][lrow] = b0.z; Bs[lcol + 3][lrow] = b0.w;
        Bs[lcol + 0][lrow + 64] = b1.x; Bs[lcol + 1][lrow + 64] = b1.y;
        Bs[lcol + 2][lrow + 64] = b1.z; Bs[lcol + 3][lrow + 64] = b1.w;
        __syncthreads();
        #pragma unroll
        for (int k = 0; k < 16; k++) {
            float ar[8], br[8];
            #pragma unroll
            for (int i = 0; i < 8; i++) ar[i] = As[k][ty * 8 + i];
            #pragma unroll
            for (int j = 0; j < 8; j++) br[j] = Bs[k][tx * 8 + j];
            #pragma unroll
            for (int i = 0; i < 8; i++)
                #pragma unroll
                for (int j = 0; j < 8; j++) acc[i][j] += ar[i] * br[j];
        }
    }

    float bj[8];
    #pragma unroll
    for (int j = 0; j < 8; j++) bj[j] = bias[o0 + tx * 8 + j];
    float* Cp = Cout + (size_t)(m0 + ty * 8) * LDCN + o0 + tx * 8;
    #pragma unroll
    for (int i = 0; i < 8; i++) {
        float4 v0, v1;
        v0.x = acc[i][0] + bj[0]; v0.y = acc[i][1] + bj[1];
        v0.z = acc[i][2] + bj[2]; v0.w = acc[i][3] + bj[3];
        v1.x = acc[i][4] + bj[4]; v1.y = acc[i][5] + bj[5];
        v1.z = acc[i][6] + bj[6]; v1.w = acc[i][7] + bj[7];
        *(float4*)(Cp + (size_t)i * LDCN)     = v0;
        *(float4*)(Cp + (size_t)i * LDCN + 4) = v1;
    }
}

__global__ __launch_bounds__(256) void sgemm_qkv(const float* __restrict__ w_qkv,
                                                 const float* __restrict__ b_qkv) {
    sgemm_body<C3>(g_normed, w_qkv, b_qkv, g_qkv);
}
__global__ __launch_bounds__(256) void sgemm_proj(const float* __restrict__ w_proj,
                                                  const float* __restrict__ b_proj) {
    sgemm_body<CC>(g_att, w_proj, b_proj, g_pout);
}

// ---------------- 4) attention per (n, head) ----------------
__global__ __launch_bounds__(256) void attn(const float* __restrict__ rp_k,
                                            const float* __restrict__ rp_v) {
    __shared__ float qs[16][65], ks[16][65], vs[16][65];
    __shared__ float rk[31][65], rv[31][65];
    __shared__ float ws[16][17];

    int n    = blockIdx.x;
    int head = blockIdx.y;
    int tid  = threadIdx.x;
    const float scale = 0.35355339059327373f;  // 64^-0.25

    size_t base = (size_t)n * TT * C3 + (size_t)head * CH;
    for (int e = tid; e < 3 * TT * CH; e += 256) {
        int which = e >> 10;
        int r = e & 1023;
        int t = r >> 6;
        int c = r & 63;
        float v = g_qkv[base + (size_t)t * C3 + (size_t)which * CC + c];
        if (which == 0)      qs[t][c] = v * scale;
        else if (which == 1) ks[t][c] = v * scale;
        else                 vs[t][c] = v;
    }
    for (int e = tid; e < 31 * 64; e += 256) {
        int r = e >> 6, c = e & 63;
        rk[r][c] = rp_k[(49 + r) * 64 + c];   // dist rows 49..79 (T=16 => |s-t|<=15)
        rv[r][c] = rp_v[(49 + r) * 64 + c];
    }
    __syncthreads();

    // scores: weight[i][j] = q[:,i].k[:,j] + q[:,j].rp_k[i-j+64]
    {
        int i = tid >> 4, j = tid & 15;
        int li = i - j + 15;
        float s = 0.f;
        #pragma unroll
        for (int c = 0; c < 64; c++) {
            s += qs[i][c] * ks[j][c];
            s += qs[j][c] * rk[li][c];
        }
        ws[i][j] = s;
    }
    __syncthreads();

    // row softmax (16 rows handled by threads 0..15)
    if (tid < 16) {
        float mx = -1e30f;
        #pragma unroll
        for (int j = 0; j < 16; j++) mx = fmaxf(mx, ws[tid][j]);
        float e[16]; float sum = 0.f;
        #pragma unroll
        for (int j = 0; j < 16; j++) { e[j] = __expf(ws[tid][j] - mx); sum += e[j]; }
        float inv = 1.f / sum;
        #pragma unroll
        for (int j = 0; j < 16; j++) ws[tid][j] = e[j] * inv;
    }
    __syncthreads();

    // output: a[c][t] = sum_s w[t][s]*(v[c][s] + rp_v[s-t+64][c])
    {
        int t  = tid >> 4;
        int cb = tid & 15;
        float w[16];
        #pragma unroll
        for (int s = 0; s < 16; s++) w[s] = ws[t][s];
        float accv[4] = {0.f, 0.f, 0.f, 0.f};
        #pragma unroll
        for (int s = 0; s < 16; s++) {
            int lv = s - t + 15;
            #pragma unroll
            for (int cc = 0; cc < 4; cc++) {
                int c = cb + 16 * cc;
                accv[cc] += w[s] * (vs[s][c] + rv[lv][c]);
            }
        }
        size_t orow = ((size_t)n * TT + t) * CC + (size_t)head * CH;
        #pragma unroll
        for (int cc = 0; cc < 4; cc++) g_att[orow + cb + 16 * cc] = accv[cc];
    }
}

// ---------------- 6) transpose back + residual ----------------
__global__ __launch_bounds__(256) void resid_tr(const float* __restrict__ x,
                                                float* __restrict__ out) {
    __shared__ float tile[32][33];
    int bx  = blockIdx.x;
    int hwt = bx & 31;
    int ct  = (bx >> 5) & 15;
    int t   = (bx >> 9) & 15;
    int b   = bx >> 13;
    int tid = threadIdx.x;

    // load from pout [M,512], coalesced over c
    {
        int c_l   = tid & 31;
        int hw_l0 = tid >> 5;
        #pragma unroll
        for (int p = 0; p < 4; p++) {
            int hw_l = hw_l0 + p * 8;
            int hw   = hwt * 32 + hw_l;
            size_t m = ((size_t)(b * HWc + hw)) * TT + t;
            tile[hw_l][c_l] = g_pout[m * CC + ct * 32 + c_l];
        }
    }
    __syncthreads();
    // store to [B,C,T,HW], coalesced over hw, + residual
    {
        int hw_l = tid & 31;
        int c_l0 = tid >> 5;
        int hw   = hwt * 32 + hw_l;
        #pragma unroll
        for (int p = 0; p < 4; p++) {
            int c_l = c_l0 + p * 8;
            int c   = ct * 32 + c_l;
            size_t idx = (((size_t)b * CC + c) * TT + t) * HWc + hw;
            out[idx] = x[idx] + tile[hw_l][c_l];
        }
    }
}

// ---------------- host launch ----------------
extern "C" void kernel_launch(void* const* d_in, const int* in_sizes, int n_in,
                              void* d_out, int out_size) {
    const float* x      = (const float*)d_in[0];
    const float* gamma  = (const float*)d_in[1];
    const float* beta   = (const float*)d_in[2];
    const float* w_qkv  = (const float*)d_in[3];
    const float* b_qkv  = (const float*)d_in[4];
    const float* rp_k   = (const float*)d_in[5];
    const float* rp_v   = (const float*)d_in[6];
    const float* w_proj = (const float*)d_in[7];
    const float* b_proj = (const float*)d_in[8];
    float* out = (float*)d_out;

    gn_stats<<<BB * GRP, 256>>>(x);
    norm_tr<<<BB * TT * (CC / 32) * (HWc / 32), 256>>>(x, gamma, beta);
    sgemm_qkv<<<dim3(MM / 128, C3 / 128), 256>>>(w_qkv, b_qkv);
    attn<<<dim3(NN, NH), 256>>>(rp_k, rp_v);
    sgemm_proj<<<dim3(MM / 128, CC / 128), 256>>>(w_proj, b_proj);
    resid_tr<<<BB * TT * (CC / 32) * (HWc / 32), 256>>>(x, out);
}

// round 3
// speedup vs baseline: 1.9579x; 1.9579x over previous
#include <cuda_runtime.h>
#include <cuda_fp16.h>
#include <stdint.h>
#include <math.h>

// ---------------- problem constants ----------------
constexpr int BB   = 4;
constexpr int CC   = 512;
constexpr int TT   = 16;
constexpr int HWc  = 1024;
constexpr int NN   = BB * HWc;      // 4096
constexpr int MM   = NN * TT;       // 65536
constexpr int NH   = 8;
constexpr int CH   = 64;
constexpr int GRP  = 32;
constexpr int CPG  = CC / GRP;      // 16
constexpr int C3   = 3 * CC;        // 1536
constexpr float EPSF = 1e-6f;

// ---------------- scratch (static device globals) ----------------
__device__ float g_mean[BB * GRP * HWc];
__device__ float g_rstd[BB * GRP * HWc];
__device__ __half g_nh[(size_t)MM * CC];
__device__ __half g_nl[(size_t)MM * CC];
__device__ __half g_wqh[C3 * CC], g_wql[C3 * CC];
__device__ __half g_wph[CC * CC], g_wpl[CC * CC];
__device__ float g_qkv[(size_t)MM * C3];
__device__ __half g_ah[(size_t)MM * CC];
__device__ __half g_al[(size_t)MM * CC];
__device__ float g_pout[(size_t)MM * CC];

// ---------------- helpers ----------------
__device__ __forceinline__ uint32_t smem_u32(const void* p) {
    uint32_t a;
    asm("{ .reg .u64 t; cvta.to.shared.u64 t, %1; cvt.u32.u64 %0, t; }" : "=r"(a) : "l"(p));
    return a;
}
__device__ __forceinline__ void cpasync16(uint32_t dst, const void* src) {
    asm volatile("cp.async.cg.shared.global [%0], [%1], 16;" :: "r"(dst), "l"(src));
}
__device__ __forceinline__ void ldsm4(uint32_t* r, uint32_t a) {
    asm volatile("ldmatrix.sync.aligned.m8n8.x4.shared.b16 {%0,%1,%2,%3}, [%4];"
                 : "=r"(r[0]), "=r"(r[1]), "=r"(r[2]), "=r"(r[3]) : "r"(a));
}
__device__ __forceinline__ void mma16816(float* d, const uint32_t* a, uint32_t b0, uint32_t b1) {
    asm volatile(
        "mma.sync.aligned.m16n8k16.row.col.f32.f16.f16.f32 "
        "{%0,%1,%2,%3},{%4,%5,%6,%7},{%8,%9},{%0,%1,%2,%3};"
        : "+f"(d[0]), "+f"(d[1]), "+f"(d[2]), "+f"(d[3])
        : "r"(a[0]), "r"(a[1]), "r"(a[2]), "r"(a[3]), "r"(b0), "r"(b1));
}

// ---------------- 1) group-norm statistics ----------------
__global__ __launch_bounds__(256) void gn_stats(const float* __restrict__ x) {
    int bg = blockIdx.x;
    int b  = bg >> 5;
    int g  = bg & 31;
    int tid = threadIdx.x;
    float sum[4] = {0.f,0.f,0.f,0.f};
    float sq [4] = {0.f,0.f,0.f,0.f};
    const float* base = x + ((size_t)b * CC + (size_t)g * CPG) * TT * HWc;
    for (int ct = 0; ct < CPG * TT; ct++) {
        const float* p = base + (size_t)ct * HWc;
        #pragma unroll
        for (int i = 0; i < 4; i++) {
            float v = p[tid + i * 256];
            sum[i] += v; sq[i] += v * v;
        }
    }
    #pragma unroll
    for (int i = 0; i < 4; i++) {
        int hw = tid + i * 256;
        float m   = sum[i] * (1.0f / 256.0f);
        float var = sq[i]  * (1.0f / 256.0f) - m * m;
        g_mean[(size_t)bg * HWc + hw] = m;
        g_rstd[(size_t)bg * HWc + hw] = rsqrtf(var + EPSF);
    }
}

// ---------------- 2) normalize + transpose to fp16 hi/lo [M,512] ----------------
__global__ __launch_bounds__(256) void norm_tr(const float* __restrict__ x,
                                               const float* __restrict__ gamma,
                                               const float* __restrict__ beta) {
    __shared__ float tile[32][33];
    int bx  = blockIdx.x;
    int hwt = bx & 31;
    int ct  = (bx >> 5) & 15;
    int t   = (bx >> 9) & 15;
    int b   = bx >> 13;
    int tid = threadIdx.x;
    {
        int hw_l = tid & 31;
        int c_l0 = tid >> 5;
        int hw   = hwt * 32 + hw_l;
        #pragma unroll
        for (int p = 0; p < 4; p++) {
            int c_l = c_l0 + p * 8;
            int c   = ct * 32 + c_l;
            int g   = c >> 4;
            float v = x[(((size_t)b * CC + c) * TT + t) * HWc + hw];
            size_t si = ((size_t)(b * GRP + g)) * HWc + hw;
            v = (v - g_mean[si]) * g_rstd[si] * gamma[c] + beta[c];
            tile[c_l][hw_l] = v;
        }
    }
    __syncthreads();
    {
        int c_l   = tid & 31;
        int hw_l0 = tid >> 5;
        #pragma unroll
        for (int p = 0; p < 4; p++) {
            int hw_l = hw_l0 + p * 8;
            int hw   = hwt * 32 + hw_l;
            size_t m = ((size_t)(b * HWc + hw)) * TT + t;
            float v = tile[c_l][hw_l];
            __half hi = __float2half(v);
            float r = v - __half2float(hi);
            size_t idx = m * CC + ct * 32 + c_l;
            g_nh[idx] = hi;
            g_nl[idx] = __float2half(r);
        }
    }
}

// ---------------- weight split fp32 -> fp16 hi/lo ----------------
__global__ __launch_bounds__(256) void conv_split(const float* __restrict__ src,
                                                  __half* __restrict__ h,
                                                  __half* __restrict__ l, int n) {
    int i = blockIdx.x * 256 + threadIdx.x;
    if (i < n) {
        float v = src[i];
        __half hi = __float2half(v);
        h[i] = hi;
        l[i] = __float2half(v - __half2float(hi));
    }
}

// ---------------- HMMA GEMM: C[M,NOUT] = A[M,512] * W[NOUT,512]^T + bias ----------------
// fp16 hi/lo split (3 passes), CTA 128x128, BK=32, 3-stage cp.async, 8 warps (64x32 each).
constexpr int PITCH   = 80;            // bytes per smem row (32 fp16 + pad)
constexpr int TILE_B  = 128 * PITCH;   // 10240
constexpr int STAGE_B = 4 * TILE_B;    // 40960 (Ah, Al, Bh, Bl)
constexpr int GEMM_SMEM = 3 * STAGE_B; // 122880

__global__ __launch_bounds__(256, 1) void hmma_gemm(const __half* __restrict__ Ah,
                                                    const __half* __restrict__ Al,
                                                    const __half* __restrict__ Bh,
                                                    const __half* __restrict__ Bl,
                                                    const float* __restrict__ bias,
                                                    float* __restrict__ Cout, int ldc) {
    extern __shared__ char smem[];
    uint32_t sb = smem_u32(smem);
    int tid = threadIdx.x;
    int n0 = blockIdx.x * 128;
    int m0 = blockIdx.y * 128;

    const int4* gAh = (const int4*)Ah;
    const int4* gAl = (const int4*)Al;
    const int4* gBh = (const int4*)Bh;
    const int4* gBl = (const int4*)Bl;

    // per-stage loader: 2048 16B chunks, 8 per thread
    auto issue = [&](int kk, int stage) {
        #pragma unroll
        for (int it = 0; it < 8; it++) {
            int i = it * 256 + tid;
            int t4 = i >> 9;            // 0=Ah 1=Al 2=Bh 3=Bl
            int r  = (i >> 2) & 127;
            int c  = i & 3;
            int row0 = (t4 < 2) ? m0 : n0;
            size_t goff = (size_t)(row0 + r) * 64 + kk * 4 + c;
            const int4* src = (t4 == 0) ? gAh + goff :
                              (t4 == 1) ? gAl + goff :
                              (t4 == 2) ? gBh + goff : gBl + goff;
            uint32_t dst = sb + stage * STAGE_B + t4 * TILE_B + r * PITCH + c * 16;
            cpasync16(dst, src);
        }
        asm volatile("cp.async.commit_group;");
    };

    float acc[4][4][4];
    #pragma unroll
    for (int a = 0; a < 4; a++)
        #pragma unroll
        for (int b = 0; b < 4; b++)
            #pragma unroll
            for (int c = 0; c < 4; c++) acc[a][b][c] = 0.f;

    int wid = tid >> 5, lane = tid & 31;
    int mw  = (wid >> 2) * 64;
    int nwv = (wid & 3) * 32;
    int lrow = lane & 15;
    int lk   = (lane >> 4) * 16;

    issue(0, 0);
    issue(1, 1);

    for (int ks = 0; ks < 16; ks++) {
        asm volatile("cp.async.wait_group 1;");
        __syncthreads();
        if (ks + 2 < 16) issue(ks + 2, (ks + 2) % 3);
        else asm volatile("cp.async.commit_group;");

        uint32_t sa = sb + (ks % 3) * STAGE_B;
        #pragma unroll
        for (int j = 0; j < 2; j++) {
            uint32_t ah[4][4], al[4][4], bh[2][4], bl[2][4];
            #pragma unroll
            for (int mt = 0; mt < 4; mt++) {
                uint32_t ad = sa + (mw + mt * 16 + lrow) * PITCH + j * 32 + lk;
                ldsm4(ah[mt], ad);
                ldsm4(al[mt], ad + TILE_B);
            }
            #pragma unroll
            for (int bt = 0; bt < 2; bt++) {
                uint32_t bd = sa + 2 * TILE_B + (nwv + bt * 16 + lrow) * PITCH + j * 32 + lk;
                ldsm4(bh[bt], bd);
                ldsm4(bl[bt], bd + TILE_B);
            }
            #pragma unroll
            for (int mt = 0; mt < 4; mt++)
                #pragma unroll
                for (int nt = 0; nt < 4; nt++) {
                    int bt = nt >> 1, s = nt & 1;
                    mma16816(acc[mt][nt], ah[mt], bh[bt][s], bh[bt][2 + s]);
                    mma16816(acc[mt][nt], ah[mt], bl[bt][s], bl[bt][2 + s]);
                    mma16816(acc[mt][nt], al[mt], bh[bt][s], bh[bt][2 + s]);
                }
        }
    }
    asm volatile("cp.async.wait_group 0;");

    // epilogue: direct fp32 stores + bias
    int row_in = lane >> 2;
    int colq   = (lane & 3) * 2;
    #pragma unroll
    for (int mt = 0; mt < 4; mt++) {
        int gr = m0 + mw + mt * 16 + row_in;
        #pragma unroll
        for (int nt = 0; nt < 4; nt++) {
            int gc = n0 + nwv + nt * 8 + colq;
            float b0 = bias[gc], b1 = bias[gc + 1];
            float2 v0 = make_float2(acc[mt][nt][0] + b0, acc[mt][nt][1] + b1);
            float2 v1 = make_float2(acc[mt][nt][2] + b0, acc[mt][nt][3] + b1);
            *(float2*)(Cout + (size_t)gr * ldc + gc)       = v0;
            *(float2*)(Cout + (size_t)(gr + 8) * ldc + gc) = v1;
        }
    }
}

// ---------------- 4) attention per (n, head), float4 smem ----------------
__global__ __launch_bounds__(256) void attn(const float* __restrict__ rp_k,
                                            const float* __restrict__ rp_v) {
    __shared__ float4 qs[16][17], ks[16][17], vs[16][17];
    __shared__ float4 rk[31][17], rv[31][17];
    __shared__ float ws[16][17];

    int n    = blockIdx.x;
    int head = blockIdx.y;
    int tid  = threadIdx.x;
    const float scale = 0.35355339059327373f;  // 64^-0.25

    const float4* gq = reinterpret_cast<const float4*>(g_qkv);
    #pragma unroll
    for (int e = tid; e < 768; e += 256) {
        int which = e >> 8;
        int r = e & 255;
        int t = r >> 4, c4 = r & 15;
        float4 v = gq[(size_t)(n * TT + t) * (C3 / 4) + which * (CC / 4) + head * (CH / 4) + c4];
        if (which == 0) { v.x *= scale; v.y *= scale; v.z *= scale; v.w *= scale; qs[t][c4] = v; }
        else if (which == 1) { v.x *= scale; v.y *= scale; v.z *= scale; v.w *= scale; ks[t][c4] = v; }
        else vs[t][c4] = v;
    }
    const float4* grk = reinterpret_cast<const float4*>(rp_k);
    const float4* grv = reinterpret_cast<const float4*>(rp_v);
    for (int e = tid; e < 992; e += 256) {
        int a = (e >= 496);
        int r = a ? e - 496 : e;
        int rr = r >> 4, c4 = r & 15;
        if (a) rv[rr][c4] = grv[(49 + rr) * 16 + c4];
        else   rk[rr][c4] = grk[(49 + rr) * 16 + c4];
    }
    __syncthreads();

    {
        int i = tid >> 4, j = tid & 15;
        int li = i - j + 15;
        float s = 0.f;
        #pragma unroll
        for (int c4 = 0; c4 < 16; c4++) {
            float4 a  = qs[i][c4];
            float4 b  = ks[j][c4];
            float4 a2 = qs[j][c4];
            float4 r  = rk[li][c4];
            s += a.x * b.x + a.y * b.y + a.z * b.z + a.w * b.w;
            s += a2.x * r.x + a2.y * r.y + a2.z * r.z + a2.w * r.w;
        }
        ws[i][j] = s;
    }
    __syncthreads();

    if (tid < 16) {
        float mx = -1e30f;
        #pragma unroll
        for (int j = 0; j < 16; j++) mx = fmaxf(mx, ws[tid][j]);
        float e[16]; float sum = 0.f;
        #pragma unroll
        for (int j = 0; j < 16; j++) { e[j] = __expf(ws[tid][j] - mx); sum += e[j]; }
        float inv = 1.f / sum;
        #pragma unroll
        for (int j = 0; j < 16; j++) ws[tid][j] = e[j] * inv;
    }
    __syncthreads();

    {
        int t  = tid >> 4;
        int cb = tid & 15;
        float4 acc = make_float4(0.f, 0.f, 0.f, 0.f);
        #pragma unroll
        for (int s = 0; s < 16; s++) {
            float wgt = ws[t][s];
            float4 v = vs[s][cb];
            float4 r = rv[s - t + 15][cb];
            acc.x += wgt * (v.x + r.x);
            acc.y += wgt * (v.y + r.y);
            acc.z += wgt * (v.z + r.z);
            acc.w += wgt * (v.w + r.w);
        }
        size_t idx = ((size_t)(n * TT + t)) * CC + head * CH + cb * 4;
        float o[4] = {acc.x, acc.y, acc.z, acc.w};
        __half h[4], l[4];
        #pragma unroll
        for (int k = 0; k < 4; k++) {
            h[k] = __float2half(o[k]);
            l[k] = __float2half(o[k] - __half2float(h[k]));
        }
        *(__half2*)(g_ah + idx)     = __halves2half2(h[0], h[1]);
        *(__half2*)(g_ah + idx + 2) = __halves2half2(h[2], h[3]);
        *(__half2*)(g_al + idx)     = __halves2half2(l[0], l[1]);
        *(__half2*)(g_al + idx + 2) = __halves2half2(l[2], l[3]);
    }
}

// ---------------- 6) transpose back + residual ----------------
__global__ __launch_bounds__(256) void resid_tr(const float* __restrict__ x,
                                                float* __restrict__ out) {
    __shared__ float tile[32][33];
    int bx  = blockIdx.x;
    int hwt = bx & 31;
    int ct  = (bx >> 5) & 15;
    int t   = (bx >> 9) & 15;
    int b   = bx >> 13;
    int tid = threadIdx.x;
    {
        int c_l   = tid & 31;
        int hw_l0 = tid >> 5;
        #pragma unroll
        for (int p = 0; p < 4; p++) {
            int hw_l = hw_l0 + p * 8;
            int hw   = hwt * 32 + hw_l;
            size_t m = ((size_t)(b * HWc + hw)) * TT + t;
            tile[hw_l][c_l] = g_pout[m * CC + ct * 32 + c_l];
        }
    }
    __syncthreads();
    {
        int hw_l = tid & 31;
        int c_l0 = tid >> 5;
        int hw   = hwt * 32 + hw_l;
        #pragma unroll
        for (int p = 0; p < 4; p++) {
            int c_l = c_l0 + p * 8;
            int c   = ct * 32 + c_l;
            size_t idx = (((size_t)b * CC + c) * TT + t) * HWc + hw;
            out[idx] = x[idx] + tile[hw_l][c_l];
        }
    }
}

// ---------------- host launch ----------------
extern "C" void kernel_launch(void* const* d_in, const int* in_sizes, int n_in,
                              void* d_out, int out_size) {
    const float* x      = (const float*)d_in[0];
    const float* gamma  = (const float*)d_in[1];
    const float* beta   = (const float*)d_in[2];
    const float* w_qkv  = (const float*)d_in[3];
    const float* b_qkv  = (const float*)d_in[4];
    const float* rp_k   = (const float*)d_in[5];
    const float* rp_v   = (const float*)d_in[6];
    const float* w_proj = (const float*)d_in[7];
    const float* b_proj = (const float*)d_in[8];
    float* out = (float*)d_out;

    cudaFuncSetAttribute(hmma_gemm, cudaFuncAttributeMaxDynamicSharedMemorySize, GEMM_SMEM);

    __half *wqh, *wql, *wph, *wpl, *nh, *nl, *ah, *al;
    cudaGetSymbolAddress((void**)&wqh, g_wqh);
    cudaGetSymbolAddress((void**)&wql, g_wql);
    cudaGetSymbolAddress((void**)&wph, g_wph);
    cudaGetSymbolAddress((void**)&wpl, g_wpl);
    cudaGetSymbolAddress((void**)&nh, g_nh);
    cudaGetSymbolAddress((void**)&nl, g_nl);
    cudaGetSymbolAddress((void**)&ah, g_ah);
    cudaGetSymbolAddress((void**)&al, g_al);
    float *qkv, *pout;
    cudaGetSymbolAddress((void**)&qkv, g_qkv);
    cudaGetSymbolAddress((void**)&pout, g_pout);

    gn_stats<<<BB * GRP, 256>>>(x);
    norm_tr<<<BB * TT * (CC / 32) * (HWc / 32), 256>>>(x, gamma, beta);
    conv_split<<<(C3 * CC + 255) / 256, 256>>>(w_qkv, wqh, wql, C3 * CC);
    conv_split<<<(CC * CC + 255) / 256, 256>>>(w_proj, wph, wpl, CC * CC);

    hmma_gemm<<<dim3(C3 / 128, MM / 128), 256, GEMM_SMEM>>>(nh, nl, wqh, wql, b_qkv, qkv, C3);
    attn<<<dim3(NN, NH), 256>>>(rp_k, rp_v);
    hmma_gemm<<<dim3(CC / 128, MM / 128), 256, GEMM_SMEM>>>(ah, al, wph, wpl, b_proj, pout, CC);
    resid_tr<<<BB * TT * (CC / 32) * (HWc / 32), 256>>>(x, out);
}

// round 4
// speedup vs baseline: 1.9716x; 1.0070x over previous
#include <cuda_runtime.h>
#include <cuda_fp16.h>
#include <stdint.h>
#include <math.h>

// ---------------- problem constants ----------------
constexpr int BB   = 4;
constexpr int CC   = 512;
constexpr int TT   = 16;
constexpr int HWc  = 1024;
constexpr int NN   = BB * HWc;      // 4096
constexpr int MM   = NN * TT;       // 65536
constexpr int NH   = 8;
constexpr int CH   = 64;
constexpr int GRP  = 32;
constexpr int CPG  = CC / GRP;      // 16
constexpr int C3   = 3 * CC;        // 1536
constexpr float EPSF = 1e-6f;

// ---------------- scratch (static device globals) ----------------
__device__ float g_ps[2][8][128][1024];   // partial sums for GN stats
__device__ float g_mean[BB * GRP * HWc];
__device__ float g_rstd[BB * GRP * HWc];
__device__ __half g_nh[(size_t)MM * CC];
__device__ __half g_nl[(size_t)MM * CC];
__device__ __half g_wqh[C3 * CC], g_wql[C3 * CC];
__device__ __half g_wph[CC * CC], g_wpl[CC * CC];
__device__ float g_qkv[(size_t)MM * C3];
__device__ __half g_ah[(size_t)MM * CC];
__device__ __half g_al[(size_t)MM * CC];
__device__ float g_pout[(size_t)MM * CC];

// ---------------- helpers ----------------
__device__ __forceinline__ uint32_t smem_u32(const void* p) {
    uint32_t a;
    asm("{ .reg .u64 t; cvta.to.shared.u64 t, %1; cvt.u32.u64 %0, t; }" : "=r"(a) : "l"(p));
    return a;
}
__device__ __forceinline__ void cpasync16(uint32_t dst, const void* src) {
    asm volatile("cp.async.cg.shared.global [%0], [%1], 16;" :: "r"(dst), "l"(src));
}
__device__ __forceinline__ void ldsm4(uint32_t* r, uint32_t a) {
    asm volatile("ldmatrix.sync.aligned.m8n8.x4.shared.b16 {%0,%1,%2,%3}, [%4];"
                 : "=r"(r[0]), "=r"(r[1]), "=r"(r[2]), "=r"(r[3]) : "r"(a));
}
__device__ __forceinline__ void mma16816(float* d, const uint32_t* a, uint32_t b0, uint32_t b1) {
    asm volatile(
        "mma.sync.aligned.m16n8k16.row.col.f32.f16.f16.f32 "
        "{%0,%1,%2,%3},{%4,%5,%6,%7},{%8,%9},{%0,%1,%2,%3};"
        : "+f"(d[0]), "+f"(d[1]), "+f"(d[2]), "+f"(d[3])
        : "r"(a[0]), "r"(a[1]), "r"(a[2]), "r"(a[3]), "r"(b0), "r"(b1));
}
__device__ __forceinline__ float dot4(float4 a, float4 b) {
    return a.x * b.x + a.y * b.y + a.z * b.z + a.w * b.w;
}

// ---------------- 1a) group-norm partial statistics ----------------
__global__ __launch_bounds__(256) void gn_part(const float* __restrict__ x) {
    int bx = blockIdx.x;          // 0..1023
    int bg = bx >> 3;             // (b,g)
    int chunk = bx & 7;           // ct chunk of 32
    int b = bg >> 5, g = bg & 31;
    int tid = threadIdx.x;
    float sum[4] = {0.f,0.f,0.f,0.f};
    float sq [4] = {0.f,0.f,0.f,0.f};
    const float* base = x + ((size_t)b * CC + (size_t)g * CPG) * TT * HWc
                          + (size_t)chunk * 32 * HWc;
    for (int ct = 0; ct < 32; ct++) {
        const float* p = base + (size_t)ct * HWc;
        #pragma unroll
        for (int i = 0; i < 4; i++) {
            float v = p[tid + i * 256];
            sum[i] += v; sq[i] += v * v;
        }
    }
    #pragma unroll
    for (int i = 0; i < 4; i++) {
        int hw = tid + i * 256;
        g_ps[0][chunk][bg][hw] = sum[i];
        g_ps[1][chunk][bg][hw] = sq[i];
    }
}

// ---------------- 1b) reduce partials ----------------
__global__ __launch_bounds__(256) void gn_red() {
    int bg = blockIdx.x;
    int tid = threadIdx.x;
    #pragma unroll
    for (int i = 0; i < 4; i++) {
        int hw = tid + i * 256;
        float s = 0.f, q = 0.f;
        #pragma unroll
        for (int c = 0; c < 8; c++) { s += g_ps[0][c][bg][hw]; q += g_ps[1][c][bg][hw]; }
        float m   = s * (1.0f / 256.0f);
        float var = q * (1.0f / 256.0f) - m * m;
        g_mean[(size_t)bg * HWc + hw] = m;
        g_rstd[(size_t)bg * HWc + hw] = rsqrtf(var + EPSF);
    }
}

// ---------------- 2) normalize + transpose to fp16 hi/lo [M,512] ----------------
__global__ __launch_bounds__(256) void norm_tr(const float* __restrict__ x,
                                               const float* __restrict__ gamma,
                                               const float* __restrict__ beta) {
    __shared__ float tile[32][33];
    int bx  = blockIdx.x;
    int hwt = bx & 31;
    int ct  = (bx >> 5) & 15;
    int t   = (bx >> 9) & 15;
    int b   = bx >> 13;
    int tid = threadIdx.x;
    {
        int hw_l = tid & 31;
        int c_l0 = tid >> 5;
        int hw   = hwt * 32 + hw_l;
        #pragma unroll
        for (int p = 0; p < 4; p++) {
            int c_l = c_l0 + p * 8;
            int c   = ct * 32 + c_l;
            int g   = c >> 4;
            float v = x[(((size_t)b * CC + c) * TT + t) * HWc + hw];
            size_t si = ((size_t)(b * GRP + g)) * HWc + hw;
            v = (v - g_mean[si]) * g_rstd[si] * gamma[c] + beta[c];
            tile[c_l][hw_l] = v;
        }
    }
    __syncthreads();
    {
        int c_l   = tid & 31;
        int hw_l0 = tid >> 5;
        #pragma unroll
        for (int p = 0; p < 4; p++) {
            int hw_l = hw_l0 + p * 8;
            int hw   = hwt * 32 + hw_l;
            size_t m = ((size_t)(b * HWc + hw)) * TT + t;
            float v = tile[c_l][hw_l];
            __half hi = __float2half(v);
            float r = v - __half2float(hi);
            size_t idx = m * CC + ct * 32 + c_l;
            g_nh[idx] = hi;
            g_nl[idx] = __float2half(r);
        }
    }
}

// ---------------- weight split fp32 -> fp16 hi/lo ----------------
__global__ __launch_bounds__(256) void conv_split(const float* __restrict__ src,
                                                  __half* __restrict__ h,
                                                  __half* __restrict__ l, int n) {
    int i = blockIdx.x * 256 + threadIdx.x;
    if (i < n) {
        float v = src[i];
        __half hi = __float2half(v);
        h[i] = hi;
        l[i] = __float2half(v - __half2float(hi));
    }
}

// ---------------- HMMA GEMM (unchanged from R3) ----------------
constexpr int PITCH   = 80;
constexpr int TILE_B  = 128 * PITCH;
constexpr int STAGE_B = 4 * TILE_B;
constexpr int GEMM_SMEM = 3 * STAGE_B;

__global__ __launch_bounds__(256, 1) void hmma_gemm(const __half* __restrict__ Ah,
                                                    const __half* __restrict__ Al,
                                                    const __half* __restrict__ Bh,
                                                    const __half* __restrict__ Bl,
                                                    const float* __restrict__ bias,
                                                    float* __restrict__ Cout, int ldc) {
    extern __shared__ char smem[];
    uint32_t sb = smem_u32(smem);
    int tid = threadIdx.x;
    int n0 = blockIdx.x * 128;
    int m0 = blockIdx.y * 128;

    const int4* gAh = (const int4*)Ah;
    const int4* gAl = (const int4*)Al;
    const int4* gBh = (const int4*)Bh;
    const int4* gBl = (const int4*)Bl;

    auto issue = [&](int kk, int stage) {
        #pragma unroll
        for (int it = 0; it < 8; it++) {
            int i = it * 256 + tid;
            int t4 = i >> 9;
            int r  = (i >> 2) & 127;
            int c  = i & 3;
            int row0 = (t4 < 2) ? m0 : n0;
            size_t goff = (size_t)(row0 + r) * 64 + kk * 4 + c;
            const int4* src = (t4 == 0) ? gAh + goff :
                              (t4 == 1) ? gAl + goff :
                              (t4 == 2) ? gBh + goff : gBl + goff;
            uint32_t dst = sb + stage * STAGE_B + t4 * TILE_B + r * PITCH + c * 16;
            cpasync16(dst, src);
        }
        asm volatile("cp.async.commit_group;");
    };

    float acc[4][4][4];
    #pragma unroll
    for (int a = 0; a < 4; a++)
        #pragma unroll
        for (int b = 0; b < 4; b++)
            #pragma unroll
            for (int c = 0; c < 4; c++) acc[a][b][c] = 0.f;

    int wid = tid >> 5, lane = tid & 31;
    int mw  = (wid >> 2) * 64;
    int nwv = (wid & 3) * 32;
    int lrow = lane & 15;
    int lk   = (lane >> 4) * 16;

    issue(0, 0);
    issue(1, 1);

    for (int ks = 0; ks < 16; ks++) {
        asm volatile("cp.async.wait_group 1;");
        __syncthreads();
        if (ks + 2 < 16) issue(ks + 2, (ks + 2) % 3);
        else asm volatile("cp.async.commit_group;");

        uint32_t sa = sb + (ks % 3) * STAGE_B;
        #pragma unroll
        for (int j = 0; j < 2; j++) {
            uint32_t ah[4][4], al[4][4], bh[2][4], bl[2][4];
            #pragma unroll
            for (int mt = 0; mt < 4; mt++) {
                uint32_t ad = sa + (mw + mt * 16 + lrow) * PITCH + j * 32 + lk;
                ldsm4(ah[mt], ad);
                ldsm4(al[mt], ad + TILE_B);
            }
            #pragma unroll
            for (int bt = 0; bt < 2; bt++) {
                uint32_t bd = sa + 2 * TILE_B + (nwv + bt * 16 + lrow) * PITCH + j * 32 + lk;
                ldsm4(bh[bt], bd);
                ldsm4(bl[bt], bd + TILE_B);
            }
            #pragma unroll
            for (int mt = 0; mt < 4; mt++)
                #pragma unroll
                for (int nt = 0; nt < 4; nt++) {
                    int bt = nt >> 1, s = nt & 1;
                    mma16816(acc[mt][nt], ah[mt], bh[bt][s], bh[bt][2 + s]);
                    mma16816(acc[mt][nt], ah[mt], bl[bt][s], bl[bt][2 + s]);
                    mma16816(acc[mt][nt], al[mt], bh[bt][s], bh[bt][2 + s]);
                }
        }
    }
    asm volatile("cp.async.wait_group 0;");

    int row_in = lane >> 2;
    int colq   = (lane & 3) * 2;
    #pragma unroll
    for (int mt = 0; mt < 4; mt++) {
        int gr = m0 + mw + mt * 16 + row_in;
        #pragma unroll
        for (int nt = 0; nt < 4; nt++) {
            int gc = n0 + nwv + nt * 8 + colq;
            float b0 = bias[gc], b1 = bias[gc + 1];
            float2 v0 = make_float2(acc[mt][nt][0] + b0, acc[mt][nt][1] + b1);
            float2 v1 = make_float2(acc[mt][nt][2] + b0, acc[mt][nt][3] + b1);
            *(float2*)(Cout + (size_t)gr * ldc + gc)       = v0;
            *(float2*)(Cout + (size_t)(gr + 8) * ldc + gc) = v1;
        }
    }
}

// ---------------- 4) attention: one block per n, all 8 heads ----------------
// smem layout (floats): q[16][516] k[16][516] v[16][516] rk[31][68] rv[31][68] ws[8][16][17]
constexpr int QP = 516;
constexpr int RP = 68;
constexpr int OFF_Q  = 0;
constexpr int OFF_K  = 16 * QP;
constexpr int OFF_V  = 32 * QP;
constexpr int OFF_RK = 48 * QP;            // 24768
constexpr int OFF_RV = OFF_RK + 31 * RP;   // 26876
constexpr int OFF_WS = OFF_RV + 31 * RP;   // 28984
constexpr int ATTN_SMEM = (OFF_WS + 8 * 16 * 17) * 4;  // 124640 B

__global__ __launch_bounds__(256, 1) void attn(const float* __restrict__ rp_k,
                                               const float* __restrict__ rp_v) {
    extern __shared__ float sm[];
    float* q  = sm + OFF_Q;
    float* k  = sm + OFF_K;
    float* v  = sm + OFF_V;
    float* rk = sm + OFF_RK;
    float* rv = sm + OFF_RV;
    float* ws = sm + OFF_WS;

    int n   = blockIdx.x;
    int tid = threadIdx.x;
    const float scale = 0.35355339059327373f;  // 64^-0.25

    // load qkv: 16 rows x 384 float4
    const float4* gq = reinterpret_cast<const float4*>(g_qkv);
    #pragma unroll
    for (int it = 0; it < 24; it++) {
        int idx = it * 256 + tid;
        int t   = idx / 384;
        int rem = idx - t * 384;
        int which = rem >> 7;
        int c4    = rem & 127;
        float4 val = gq[(size_t)(n * TT + t) * 384 + rem];
        if (which < 2) { val.x *= scale; val.y *= scale; val.z *= scale; val.w *= scale; }
        float* dst = (which == 0 ? q : which == 1 ? k : v) + t * QP + c4 * 4;
        *(float4*)dst = val;
    }
    // load rp: 2 x 496 float4
    const float4* grk = reinterpret_cast<const float4*>(rp_k);
    const float4* grv = reinterpret_cast<const float4*>(rp_v);
    for (int idx = tid; idx < 992; idx += 256) {
        int half = idx >= 496;
        int r = idx - half * 496;
        int row = r >> 4, c4 = r & 15;
        float4 val = (half ? grv : grk)[(49 + row) * 16 + c4];
        *(float4*)((half ? rv : rk) + row * RP + c4 * 4) = val;
    }
    __syncthreads();

    // ---- score phase: 8 heads x 16 tiles(4x4) x 2 channel-halves ----
    {
        int h = tid >> 5;
        int r5 = tid & 31;
        int tile = r5 & 15;
        int chalf = r5 >> 4;
        int ti = (tile >> 2) << 2;
        int tj = (tile & 3) << 2;
        int cbase = h * 64 + chalf * 32;
        const float* rkb = rk + (ti - tj + 12) * RP + chalf * 32;

        float acc[4][4];
        #pragma unroll
        for (int a = 0; a < 4; a++)
            #pragma unroll
            for (int b = 0; b < 4; b++) acc[a][b] = 0.f;

        #pragma unroll
        for (int c4 = 0; c4 < 8; c4++) {
            int c = cbase + c4 * 4;
            float4 qi[4], kj[4], qj[4], rr[7];
            #pragma unroll
            for (int a = 0; a < 4; a++) qi[a] = *(const float4*)(q + (ti + a) * QP + c);
            #pragma unroll
            for (int b = 0; b < 4; b++) {
                kj[b] = *(const float4*)(k + (tj + b) * QP + c);
                qj[b] = *(const float4*)(q + (tj + b) * QP + c);
            }
            #pragma unroll
            for (int e = 0; e < 7; e++) rr[e] = *(const float4*)(rkb + e * RP + c4 * 4);
            #pragma unroll
            for (int a = 0; a < 4; a++)
                #pragma unroll
                for (int b = 0; b < 4; b++)
                    acc[a][b] += dot4(qi[a], kj[b]) + dot4(qj[b], rr[a - b + 3]);
        }
        // combine channel halves (partner = lane ^ 16)
        #pragma unroll
        for (int a = 0; a < 4; a++)
            #pragma unroll
            for (int b = 0; b < 4; b++) {
                acc[a][b] += __shfl_xor_sync(0xFFFFFFFFu, acc[a][b], 16);
                if (chalf == 0) ws[h * 272 + (ti + a) * 17 + tj + b] = acc[a][b];
            }
    }
    __syncthreads();

    // ---- softmax: 128 threads, one (h, row) each ----
    if (tid < 128) {
        int h = tid >> 4, i = tid & 15;
        float* wp = ws + h * 272 + i * 17;
        float mx = -1e30f;
        #pragma unroll
        for (int j = 0; j < 16; j++) mx = fmaxf(mx, wp[j]);
        float e[16]; float sum = 0.f;
        #pragma unroll
        for (int j = 0; j < 16; j++) { e[j] = __expf(wp[j] - mx); sum += e[j]; }
        float inv = 1.f / sum;
        #pragma unroll
        for (int j = 0; j < 16; j++) wp[j] = e[j] * inv;
    }
    __syncthreads();

    // ---- output phase: 8 heads x 4 t-groups x 8 channel-octets ----
    {
        int h = tid >> 5;
        int r5 = tid & 31;
        int tgrp = r5 >> 3;
        int cq = r5 & 7;
        int t0 = tgrp * 4;
        int c = h * 64 + cq * 8;
        const float* wsb = ws + h * 272;

        float acc[4][8];
        #pragma unroll
        for (int t = 0; t < 4; t++)
            #pragma unroll
            for (int j = 0; j < 8; j++) acc[t][j] = 0.f;

        // content term
        #pragma unroll
        for (int s = 0; s < 16; s++) {
            float4 v0 = *(const float4*)(v + s * QP + c);
            float4 v1 = *(const float4*)(v + s * QP + c + 4);
            #pragma unroll
            for (int t = 0; t < 4; t++) {
                float wv = wsb[(t0 + t) * 17 + s];
                acc[t][0] += wv * v0.x; acc[t][1] += wv * v0.y;
                acc[t][2] += wv * v0.z; acc[t][3] += wv * v0.w;
                acc[t][4] += wv * v1.x; acc[t][5] += wv * v1.y;
                acc[t][6] += wv * v1.z; acc[t][7] += wv * v1.w;
            }
        }
        // relative term: rv row d serves all t with s = d + t - 15 in range
        #pragma unroll
        for (int d = 0; d < 31; d++) {
            float4 r0 = *(const float4*)(rv + d * RP + cq * 8);
            float4 r1 = *(const float4*)(rv + d * RP + cq * 8 + 4);
            #pragma unroll
            for (int t = 0; t < 4; t++) {
                int s = d + t0 + t - 15;
                if (s >= 0 && s < 16) {
                    float wv = wsb[(t0 + t) * 17 + s];
                    acc[t][0] += wv * r0.x; acc[t][1] += wv * r0.y;
                    acc[t][2] += wv * r0.z; acc[t][3] += wv * r0.w;
                    acc[t][4] += wv * r1.x; acc[t][5] += wv * r1.y;
                    acc[t][6] += wv * r1.z; acc[t][7] += wv * r1.w;
                }
            }
        }
        // hi/lo split + store
        #pragma unroll
        for (int t = 0; t < 4; t++) {
            size_t idx = ((size_t)(n * TT + t0 + t)) * CC + c;
            uint4 uh, ul;
            __half hh[8], ll[8];
            #pragma unroll
            for (int j = 0; j < 8; j++) {
                hh[j] = __float2half(acc[t][j]);
                ll[j] = __float2half(acc[t][j] - __half2float(hh[j]));
            }
            uh.x = *(uint32_t*)&hh[0]; uh.y = *(uint32_t*)&hh[2];
            uh.z = *(uint32_t*)&hh[4]; uh.w = *(uint32_t*)&hh[6];
            ul.x = *(uint32_t*)&ll[0]; ul.y = *(uint32_t*)&ll[2];
            ul.z = *(uint32_t*)&ll[4]; ul.w = *(uint32_t*)&ll[6];
            *(uint4*)(g_ah + idx) = uh;
            *(uint4*)(g_al + idx) = ul;
        }
    }
}

// ---------------- 6) transpose back + residual ----------------
__global__ __launch_bounds__(256) void resid_tr(const float* __restrict__ x,
                                                float* __restrict__ out) {
    __shared__ float tile[32][33];
    int bx  = blockIdx.x;
    int hwt = bx & 31;
    int ct  = (bx >> 5) & 15;
    int t   = (bx >> 9) & 15;
    int b   = bx >> 13;
    int tid = threadIdx.x;
    {
        int c_l   = tid & 31;
        int hw_l0 = tid >> 5;
        #pragma unroll
        for (int p = 0; p < 4; p++) {
            int hw_l = hw_l0 + p * 8;
            int hw   = hwt * 32 + hw_l;
            size_t m = ((size_t)(b * HWc + hw)) * TT + t;
            tile[hw_l][c_l] = g_pout[m * CC + ct * 32 + c_l];
        }
    }
    __syncthreads();
    {
        int hw_l = tid & 31;
        int c_l0 = tid >> 5;
        int hw   = hwt * 32 + hw_l;
        #pragma unroll
        for (int p = 0; p < 4; p++) {
            int c_l = c_l0 + p * 8;
            int c   = ct * 32 + c_l;
            size_t idx = (((size_t)b * CC + c) * TT + t) * HWc + hw;
            out[idx] = x[idx] + tile[hw_l][c_l];
        }
    }
}

// ---------------- host launch ----------------
extern "C" void kernel_launch(void* const* d_in, const int* in_sizes, int n_in,
                              void* d_out, int out_size) {
    const float* x      = (const float*)d_in[0];
    const float* gamma  = (const float*)d_in[1];
    const float* beta   = (const float*)d_in[2];
    const float* w_qkv  = (const float*)d_in[3];
    const float* b_qkv  = (const float*)d_in[4];
    const float* rp_k   = (const float*)d_in[5];
    const float* rp_v   = (const float*)d_in[6];
    const float* w_proj = (const float*)d_in[7];
    const float* b_proj = (const float*)d_in[8];
    float* out = (float*)d_out;

    cudaFuncSetAttribute(hmma_gemm, cudaFuncAttributeMaxDynamicSharedMemorySize, GEMM_SMEM);
    cudaFuncSetAttribute(attn, cudaFuncAttributeMaxDynamicSharedMemorySize, ATTN_SMEM);

    __half *wqh, *wql, *wph, *wpl, *nh, *nl, *ah, *al;
    cudaGetSymbolAddress((void**)&wqh, g_wqh);
    cudaGetSymbolAddress((void**)&wql, g_wql);
    cudaGetSymbolAddress((void**)&wph, g_wph);
    cudaGetSymbolAddress((void**)&wpl, g_wpl);
    cudaGetSymbolAddress((void**)&nh, g_nh);
    cudaGetSymbolAddress((void**)&nl, g_nl);
    cudaGetSymbolAddress((void**)&ah, g_ah);
    cudaGetSymbolAddress((void**)&al, g_al);
    float *qkv, *pout;
    cudaGetSymbolAddress((void**)&qkv, g_qkv);
    cudaGetSymbolAddress((void**)&pout, g_pout);

    gn_part<<<1024, 256>>>(x);
    gn_red<<<128, 256>>>();
    norm_tr<<<BB * TT * (CC / 32) * (HWc / 32), 256>>>(x, gamma, beta);
    conv_split<<<(C3 * CC + 255) / 256, 256>>>(w_qkv, wqh, wql, C3 * CC);
    conv_split<<<(CC * CC + 255) / 256, 256>>>(w_proj, wph, wpl, CC * CC);

    hmma_gemm<<<dim3(C3 / 128, MM / 128), 256, GEMM_SMEM>>>(nh, nl, wqh, wql, b_qkv, qkv, C3);
    attn<<<NN, 256, ATTN_SMEM>>>(rp_k, rp_v);
    hmma_gemm<<<dim3(CC / 128, MM / 128), 256, GEMM_SMEM>>>(ah, al, wph, wpl, b_proj, pout, CC);
    resid_tr<<<BB * TT * (CC / 32) * (HWc / 32), 256>>>(x, out);
}

// round 5
// speedup vs baseline: 2.1797x; 1.1055x over previous
#include <cuda_runtime.h>
#include <cuda_fp16.h>
#include <stdint.h>
#include <math.h>

// ---------------- problem constants ----------------
constexpr int BB   = 4;
constexpr int CC   = 512;
constexpr int TT   = 16;
constexpr int HWc  = 1024;
constexpr int NN   = BB * HWc;      // 4096
constexpr int MM   = NN * TT;       // 65536
constexpr int NH   = 8;
constexpr int CH   = 64;
constexpr int GRP  = 32;
constexpr int CPG  = CC / GRP;      // 16
constexpr int C3   = 3 * CC;        // 1536
constexpr float EPSF = 1e-6f;

// ---------------- scratch (static device globals) ----------------
__device__ float g_mean[BB * GRP * HWc];
__device__ float g_rstd[BB * GRP * HWc];
__device__ __half g_nh[(size_t)MM * CC];
__device__ __half g_nl[(size_t)MM * CC];
__device__ __half g_wqh[C3 * CC], g_wql[C3 * CC];
__device__ __half g_wph[CC * CC], g_wpl[CC * CC];
__device__ float g_qkv[(size_t)MM * C3];
__device__ __half g_ah[(size_t)MM * CC];
__device__ __half g_al[(size_t)MM * CC];
__device__ float g_pout[(size_t)MM * CC];

// ---------------- helpers ----------------
__device__ __forceinline__ uint32_t smem_u32(const void* p) {
    uint32_t a;
    asm("{ .reg .u64 t; cvta.to.shared.u64 t, %1; cvt.u32.u64 %0, t; }" : "=r"(a) : "l"(p));
    return a;
}
__device__ __forceinline__ void cpasync16(uint32_t dst, const void* src) {
    asm volatile("cp.async.cg.shared.global [%0], [%1], 16;" :: "r"(dst), "l"(src));
}
__device__ __forceinline__ void ldsm4(uint32_t* r, uint32_t a) {
    asm volatile("ldmatrix.sync.aligned.m8n8.x4.shared.b16 {%0,%1,%2,%3}, [%4];"
                 : "=r"(r[0]), "=r"(r[1]), "=r"(r[2]), "=r"(r[3]) : "r"(a));
}
__device__ __forceinline__ void mma16816(float* d, const uint32_t* a, uint32_t b0, uint32_t b1) {
    asm volatile(
        "mma.sync.aligned.m16n8k16.row.col.f32.f16.f16.f32 "
        "{%0,%1,%2,%3},{%4,%5,%6,%7},{%8,%9},{%0,%1,%2,%3};"
        : "+f"(d[0]), "+f"(d[1]), "+f"(d[2]), "+f"(d[3])
        : "r"(a[0]), "r"(a[1]), "r"(a[2]), "r"(a[3]), "r"(b0), "r"(b1));
}
__device__ __forceinline__ float dot4(float4 a, float4 b) {
    return a.x * b.x + a.y * b.y + a.z * b.z + a.w * b.w;
}

// ---------------- 0) split both weight matrices (one launch) ----------------
__global__ __launch_bounds__(256) void conv_both(const float* __restrict__ wq,
                                                 const float* __restrict__ wp) {
    int i4 = blockIdx.x * 256 + threadIdx.x;   // float4 index
    constexpr int NQ4 = C3 * CC / 4;           // 196608
    constexpr int NP4 = CC * CC / 4;           // 65536
    const float4* src;
    __half *h, *l;
    int idx;
    if (i4 < NQ4) { src = (const float4*)wq; h = g_wqh; l = g_wql; idx = i4; }
    else if (i4 < NQ4 + NP4) { src = (const float4*)wp; h = g_wph; l = g_wpl; idx = i4 - NQ4; }
    else return;
    float4 v = src[idx];
    float vv[4] = {v.x, v.y, v.z, v.w};
    __half hh[4], ll[4];
    #pragma unroll
    for (int k = 0; k < 4; k++) {
        hh[k] = __float2half(vv[k]);
        ll[k] = __float2half(vv[k] - __half2float(hh[k]));
    }
    uint2 uh, ul;
    uh.x = *(uint32_t*)&hh[0]; uh.y = *(uint32_t*)&hh[2];
    ul.x = *(uint32_t*)&ll[0]; ul.y = *(uint32_t*)&ll[2];
    *(uint2*)(h + idx * 4) = uh;
    *(uint2*)(l + idx * 4) = ul;
}

// ---------------- 1) group-norm statistics (fused, 1024 thr/block) ----------------
__global__ __launch_bounds__(1024) void gn_stats(const float* __restrict__ x) {
    int bg = blockIdx.x;             // 0..127 = (b,g)
    int b  = bg >> 5;
    int g  = bg & 31;
    int hw = threadIdx.x;            // 0..1023
    float sum = 0.f, sq = 0.f;
    const float* base = x + ((size_t)b * CC + (size_t)g * CPG) * TT * HWc + hw;
    #pragma unroll 4
    for (int ct = 0; ct < CPG * TT; ct++) {
        float v = base[(size_t)ct * HWc];
        sum += v; sq += v * v;
    }
    float m   = sum * (1.0f / 256.0f);
    float var = sq  * (1.0f / 256.0f) - m * m;
    g_mean[(size_t)bg * HWc + hw] = m;
    g_rstd[(size_t)bg * HWc + hw] = rsqrtf(var + EPSF);
}

// ---------------- 2) normalize + transpose to fp16 hi/lo [M,512] ----------------
__global__ __launch_bounds__(256) void norm_tr(const float* __restrict__ x,
                                               const float* __restrict__ gamma,
                                               const float* __restrict__ beta) {
    __shared__ float tile[32][33];
    int bx  = blockIdx.x;
    int hwt = bx & 31;
    int ct  = (bx >> 5) & 15;
    int t   = (bx >> 9) & 15;
    int b   = bx >> 13;
    int tid = threadIdx.x;
    {
        int hw_l = tid & 31;
        int c_l0 = tid >> 5;
        int hw   = hwt * 32 + hw_l;
        #pragma unroll
        for (int p = 0; p < 4; p++) {
            int c_l = c_l0 + p * 8;
            int c   = ct * 32 + c_l;
            int g   = c >> 4;
            float v = x[(((size_t)b * CC + c) * TT + t) * HWc + hw];
            size_t si = ((size_t)(b * GRP + g)) * HWc + hw;
            v = (v - g_mean[si]) * g_rstd[si] * gamma[c] + beta[c];
            tile[c_l][hw_l] = v;
        }
    }
    __syncthreads();
    {
        int c2    = (tid & 15) * 2;
        int hw_l0 = tid >> 4;
        #pragma unroll
        for (int p = 0; p < 2; p++) {
            int hw_l = hw_l0 + p * 16;
            int hw   = hwt * 32 + hw_l;
            size_t m = ((size_t)(b * HWc + hw)) * TT + t;
            float v0 = tile[c2][hw_l];
            float v1 = tile[c2 + 1][hw_l];
            __half h0 = __float2half(v0), h1 = __float2half(v1);
            __half l0 = __float2half(v0 - __half2float(h0));
            __half l1 = __float2half(v1 - __half2float(h1));
            size_t idx = m * CC + ct * 32 + c2;
            *(__half2*)(g_nh + idx) = __halves2half2(h0, h1);
            *(__half2*)(g_nl + idx) = __halves2half2(l0, l1);
        }
    }
}

// ---------------- HMMA GEMM: 2-stage double buffer, 2 CTAs/SM ----------------
constexpr int PITCH   = 80;            // bytes per smem row (32 fp16 + pad)
constexpr int TILE_B  = 128 * PITCH;   // 10240
constexpr int STAGE_B = 4 * TILE_B;    // 40960 (Ah, Al, Bh, Bl)
constexpr int GEMM_SMEM = 2 * STAGE_B; // 81920

__global__ __launch_bounds__(256, 2) void hmma_gemm(const __half* __restrict__ Ah,
                                                    const __half* __restrict__ Al,
                                                    const __half* __restrict__ Bh,
                                                    const __half* __restrict__ Bl,
                                                    const float* __restrict__ bias,
                                                    float* __restrict__ Cout, int ldc) {
    extern __shared__ char smem[];
    uint32_t sb = smem_u32(smem);
    int tid = threadIdx.x;
    int n0 = blockIdx.x * 128;
    int m0 = blockIdx.y * 128;

    const int4* gAh = (const int4*)Ah;
    const int4* gAl = (const int4*)Al;
    const int4* gBh = (const int4*)Bh;
    const int4* gBl = (const int4*)Bl;

    auto issue = [&](int kk, int stage) {
        #pragma unroll
        for (int it = 0; it < 8; it++) {
            int i = it * 256 + tid;
            int t4 = i >> 9;
            int r  = (i >> 2) & 127;
            int c  = i & 3;
            int row0 = (t4 < 2) ? m0 : n0;
            size_t goff = (size_t)(row0 + r) * 64 + kk * 4 + c;
            const int4* src = (t4 == 0) ? gAh + goff :
                              (t4 == 1) ? gAl + goff :
                              (t4 == 2) ? gBh + goff : gBl + goff;
            uint32_t dst = sb + stage * STAGE_B + t4 * TILE_B + r * PITCH + c * 16;
            cpasync16(dst, src);
        }
        asm volatile("cp.async.commit_group;");
    };

    float acc[4][4][4];
    #pragma unroll
    for (int a = 0; a < 4; a++)
        #pragma unroll
        for (int b = 0; b < 4; b++)
            #pragma unroll
            for (int c = 0; c < 4; c++) acc[a][b][c] = 0.f;

    int wid = tid >> 5, lane = tid & 31;
    int mw  = (wid >> 2) * 64;
    int nwv = (wid & 3) * 32;
    int lrow = lane & 15;
    int lk   = (lane >> 4) * 16;

    issue(0, 0);

    #pragma unroll 1
    for (int ks = 0; ks < 16; ks++) {
        if (ks + 1 < 16) {
            issue(ks + 1, (ks + 1) & 1);
            asm volatile("cp.async.wait_group 1;");
        } else {
            asm volatile("cp.async.wait_group 0;");
        }
        __syncthreads();

        uint32_t sa = sb + (ks & 1) * STAGE_B;
        #pragma unroll
        for (int j = 0; j < 2; j++) {
            uint32_t ah[4][4], al[4][4], bh[2][4], bl[2][4];
            #pragma unroll
            for (int mt = 0; mt < 4; mt++) {
                uint32_t ad = sa + (mw + mt * 16 + lrow) * PITCH + j * 32 + lk;
                ldsm4(ah[mt], ad);
                ldsm4(al[mt], ad + TILE_B);
            }
            #pragma unroll
            for (int bt = 0; bt < 2; bt++) {
                uint32_t bd = sa + 2 * TILE_B + (nwv + bt * 16 + lrow) * PITCH + j * 32 + lk;
                ldsm4(bh[bt], bd);
                ldsm4(bl[bt], bd + TILE_B);
            }
            #pragma unroll
            for (int mt = 0; mt < 4; mt++)
                #pragma unroll
                for (int nt = 0; nt < 4; nt++) {
                    int bt = nt >> 1, s = nt & 1;
                    mma16816(acc[mt][nt], ah[mt], bh[bt][s], bh[bt][2 + s]);
                    mma16816(acc[mt][nt], ah[mt], bl[bt][s], bl[bt][2 + s]);
                    mma16816(acc[mt][nt], al[mt], bh[bt][s], bh[bt][2 + s]);
                }
        }
        __syncthreads();
    }

    int row_in = lane >> 2;
    int colq   = (lane & 3) * 2;
    #pragma unroll
    for (int mt = 0; mt < 4; mt++) {
        int gr = m0 + mw + mt * 16 + row_in;
        #pragma unroll
        for (int nt = 0; nt < 4; nt++) {
            int gc = n0 + nwv + nt * 8 + colq;
            float b0 = bias[gc], b1 = bias[gc + 1];
            float2 v0 = make_float2(acc[mt][nt][0] + b0, acc[mt][nt][1] + b1);
            float2 v1 = make_float2(acc[mt][nt][2] + b0, acc[mt][nt][3] + b1);
            *(float2*)(Cout + (size_t)gr * ldc + gc)       = v0;
            *(float2*)(Cout + (size_t)(gr + 8) * ldc + gc) = v1;
        }
    }
}

// ---------------- 4) attention: one block per n, all 8 heads ----------------
constexpr int QP = 516;
constexpr int RP = 68;
constexpr int OFF_Q  = 0;
constexpr int OFF_K  = 16 * QP;
constexpr int OFF_V  = 32 * QP;
constexpr int OFF_RK = 48 * QP;
constexpr int OFF_RV = OFF_RK + 31 * RP;
constexpr int OFF_WS = OFF_RV + 31 * RP;
constexpr int ATTN_SMEM = (OFF_WS + 8 * 16 * 17) * 4;

__global__ __launch_bounds__(256, 1) void attn(const float* __restrict__ rp_k,
                                               const float* __restrict__ rp_v) {
    extern __shared__ float sm[];
    float* q  = sm + OFF_Q;
    float* k  = sm + OFF_K;
    float* v  = sm + OFF_V;
    float* rk = sm + OFF_RK;
    float* rv = sm + OFF_RV;
    float* ws = sm + OFF_WS;

    int n   = blockIdx.x;
    int tid = threadIdx.x;
    const float scale = 0.35355339059327373f;  // 64^-0.25

    const float4* gq = reinterpret_cast<const float4*>(g_qkv);
    #pragma unroll
    for (int it = 0; it < 24; it++) {
        int idx = it * 256 + tid;
        int t   = idx / 384;
        int rem = idx - t * 384;
        int which = rem >> 7;
        int c4    = rem & 127;
        float4 val = gq[(size_t)(n * TT + t) * 384 + rem];
        if (which < 2) { val.x *= scale; val.y *= scale; val.z *= scale; val.w *= scale; }
        float* dst = (which == 0 ? q : which == 1 ? k : v) + t * QP + c4 * 4;
        *(float4*)dst = val;
    }
    const float4* grk = reinterpret_cast<const float4*>(rp_k);
    const float4* grv = reinterpret_cast<const float4*>(rp_v);
    for (int idx = tid; idx < 992; idx += 256) {
        int half = idx >= 496;
        int r = idx - half * 496;
        int row = r >> 4, c4 = r & 15;
        float4 val = (half ? grv : grk)[(49 + row) * 16 + c4];
        *(float4*)((half ? rv : rk) + row * RP + c4 * 4) = val;
    }
    __syncthreads();

    {
        int h = tid >> 5;
        int r5 = tid & 31;
        int tile = r5 & 15;
        int chalf = r5 >> 4;
        int ti = (tile >> 2) << 2;
        int tj = (tile & 3) << 2;
        int cbase = h * 64 + chalf * 32;
        const float* rkb = rk + (ti - tj + 12) * RP + chalf * 32;

        float acc[4][4];
        #pragma unroll
        for (int a = 0; a < 4; a++)
            #pragma unroll
            for (int b = 0; b < 4; b++) acc[a][b] = 0.f;

        #pragma unroll
        for (int c4 = 0; c4 < 8; c4++) {
            int c = cbase + c4 * 4;
            float4 qi[4], kj[4], qj[4], rr[7];
            #pragma unroll
            for (int a = 0; a < 4; a++) qi[a] = *(const float4*)(q + (ti + a) * QP + c);
            #pragma unroll
            for (int b = 0; b < 4; b++) {
                kj[b] = *(const float4*)(k + (tj + b) * QP + c);
                qj[b] = *(const float4*)(q + (tj + b) * QP + c);
            }
            #pragma unroll
            for (int e = 0; e < 7; e++) rr[e] = *(const float4*)(rkb + e * RP + c4 * 4);
            #pragma unroll
            for (int a = 0; a < 4; a++)
                #pragma unroll
                for (int b = 0; b < 4; b++)
                    acc[a][b] += dot4(qi[a], kj[b]) + dot4(qj[b], rr[a - b + 3]);
        }
        #pragma unroll
        for (int a = 0; a < 4; a++)
            #pragma unroll
            for (int b = 0; b < 4; b++) {
                acc[a][b] += __shfl_xor_sync(0xFFFFFFFFu, acc[a][b], 16);
                if (chalf == 0) ws[h * 272 + (ti + a) * 17 + tj + b] = acc[a][b];
            }
    }
    __syncthreads();

    if (tid < 128) {
        int h = tid >> 4, i = tid & 15;
        float* wp = ws + h * 272 + i * 17;
        float mx = -1e30f;
        #pragma unroll
        for (int j = 0; j < 16; j++) mx = fmaxf(mx, wp[j]);
        float e[16]; float sum = 0.f;
        #pragma unroll
        for (int j = 0; j < 16; j++) { e[j] = __expf(wp[j] - mx); sum += e[j]; }
        float inv = 1.f / sum;
        #pragma unroll
        for (int j = 0; j < 16; j++) wp[j] = e[j] * inv;
    }
    __syncthreads();

    {
        int h = tid >> 5;
        int r5 = tid & 31;
        int tgrp = r5 >> 3;
        int cq = r5 & 7;
        int t0 = tgrp * 4;
        int c = h * 64 + cq * 8;
        const float* wsb = ws + h * 272;

        float acc[4][8];
        #pragma unroll
        for (int t = 0; t < 4; t++)
            #pragma unroll
            for (int j = 0; j < 8; j++) acc[t][j] = 0.f;

        #pragma unroll
        for (int s = 0; s < 16; s++) {
            float4 v0 = *(const float4*)(v + s * QP + c);
            float4 v1 = *(const float4*)(v + s * QP + c + 4);
            #pragma unroll
            for (int t = 0; t < 4; t++) {
                float wv = wsb[(t0 + t) * 17 + s];
                acc[t][0] += wv * v0.x; acc[t][1] += wv * v0.y;
                acc[t][2] += wv * v0.z; acc[t][3] += wv * v0.w;
                acc[t][4] += wv * v1.x; acc[t][5] += wv * v1.y;
                acc[t][6] += wv * v1.z; acc[t][7] += wv * v1.w;
            }
        }
        #pragma unroll
        for (int d = 0; d < 31; d++) {
            float4 r0 = *(const float4*)(rv + d * RP + cq * 8);
            float4 r1 = *(const float4*)(rv + d * RP + cq * 8 + 4);
            #pragma unroll
            for (int t = 0; t < 4; t++) {
                int s = d + t0 + t - 15;
                if (s >= 0 && s < 16) {
                    float wv = wsb[(t0 + t) * 17 + s];
                    acc[t][0] += wv * r0.x; acc[t][1] += wv * r0.y;
                    acc[t][2] += wv * r0.z; acc[t][3] += wv * r0.w;
                    acc[t][4] += wv * r1.x; acc[t][5] += wv * r1.y;
                    acc[t][6] += wv * r1.z; acc[t][7] += wv * r1.w;
                }
            }
        }
        #pragma unroll
        for (int t = 0; t < 4; t++) {
            size_t idx = ((size_t)(n * TT + t0 + t)) * CC + c;
            uint4 uh, ul;
            __half hh[8], ll[8];
            #pragma unroll
            for (int j = 0; j < 8; j++) {
                hh[j] = __float2half(acc[t][j]);
                ll[j] = __float2half(acc[t][j] - __half2float(hh[j]));
            }
            uh.x = *(uint32_t*)&hh[0]; uh.y = *(uint32_t*)&hh[2];
            uh.z = *(uint32_t*)&hh[4]; uh.w = *(uint32_t*)&hh[6];
            ul.x = *(uint32_t*)&ll[0]; ul.y = *(uint32_t*)&ll[2];
            ul.z = *(uint32_t*)&ll[4]; ul.w = *(uint32_t*)&ll[6];
            *(uint4*)(g_ah + idx) = uh;
            *(uint4*)(g_al + idx) = ul;
        }
    }
}

// ---------------- 6) transpose back + residual ----------------
__global__ __launch_bounds__(256) void resid_tr(const float* __restrict__ x,
                                                float* __restrict__ out) {
    __shared__ float tile[32][33];
    int bx  = blockIdx.x;
    int hwt = bx & 31;
    int ct  = (bx >> 5) & 15;
    int t   = (bx >> 9) & 15;
    int b   = bx >> 13;
    int tid = threadIdx.x;
    {
        int c_l   = tid & 31;
        int hw_l0 = tid >> 5;
        #pragma unroll
        for (int p = 0; p < 4; p++) {
            int hw_l = hw_l0 + p * 8;
            int hw   = hwt * 32 + hw_l;
            size_t m = ((size_t)(b * HWc + hw)) * TT + t;
            tile[hw_l][c_l] = g_pout[m * CC + ct * 32 + c_l];
        }
    }
    __syncthreads();
    {
        int hw_l = tid & 31;
        int c_l0 = tid >> 5;
        int hw   = hwt * 32 + hw_l;
        #pragma unroll
        for (int p = 0; p < 4; p++) {
            int c_l = c_l0 + p * 8;
            int c   = ct * 32 + c_l;
            size_t idx = (((size_t)b * CC + c) * TT + t) * HWc + hw;
            out[idx] = x[idx] + tile[hw_l][c_l];
        }
    }
}

// ---------------- host launch ----------------
extern "C" void kernel_launch(void* const* d_in, const int* in_sizes, int n_in,
                              void* d_out, int out_size) {
    const float* x      = (const float*)d_in[0];
    const float* gamma  = (const float*)d_in[1];
    const float* beta   = (const float*)d_in[2];
    const float* w_qkv  = (const float*)d_in[3];
    const float* b_qkv  = (const float*)d_in[4];
    const float* rp_k   = (const float*)d_in[5];
    const float* rp_v   = (const float*)d_in[6];
    const float* w_proj = (const float*)d_in[7];
    const float* b_proj = (const float*)d_in[8];
    float* out = (float*)d_out;

    cudaFuncSetAttribute(hmma_gemm, cudaFuncAttributeMaxDynamicSharedMemorySize, GEMM_SMEM);
    cudaFuncSetAttribute(attn, cudaFuncAttributeMaxDynamicSharedMemorySize, ATTN_SMEM);

    __half *wqh, *wql, *wph, *wpl, *nh, *nl, *ah, *al;
    cudaGetSymbolAddress((void**)&wqh, g_wqh);
    cudaGetSymbolAddress((void**)&wql, g_wql);
    cudaGetSymbolAddress((void**)&wph, g_wph);
    cudaGetSymbolAddress((void**)&wpl, g_wpl);
    cudaGetSymbolAddress((void**)&nh, g_nh);
    cudaGetSymbolAddress((void**)&nl, g_nl);
    cudaGetSymbolAddress((void**)&ah, g_ah);
    cudaGetSymbolAddress((void**)&al, g_al);
    float *qkv, *pout;
    cudaGetSymbolAddress((void**)&qkv, g_qkv);
    cudaGetSymbolAddress((void**)&pout, g_pout);

    // launch order chosen so hmma_gemm(qkv) is launch #4 (ncu profile target)
    conv_both<<<(C3 * CC / 4 + CC * CC / 4 + 255) / 256, 256>>>(w_qkv, w_proj);
    gn_stats<<<BB * GRP, 1024>>>(x);
    norm_tr<<<BB * TT * (CC / 32) * (HWc / 32), 256>>>(x, gamma, beta);
    hmma_gemm<<<dim3(C3 / 128, MM / 128), 256, GEMM_SMEM>>>(nh, nl, wqh, wql, b_qkv, qkv, C3);
    attn<<<NN, 256, ATTN_SMEM>>>(rp_k, rp_v);
    hmma_gemm<<<dim3(CC / 128, MM / 128), 256, GEMM_SMEM>>>(ah, al, wph, wpl, b_proj, pout, CC);
    resid_tr<<<BB * TT * (CC / 32) * (HWc / 32), 256>>>(x, out);
}